// round 15
// baseline (speedup 1.0000x reference)
#include <cuda_runtime.h>
#include <cuda_bf16.h>

#define B 64
#define L 1024
#define D 1024
#define S 32

#define DP 8            // d-partitions; each CTA covers 128 floats
#define DW 128
#define LP 4            // token-chunk partitions (raises grid to 2048)
#define LCH (L / LP)    // 256 tokens per CTA
#define TPB 128
#define U 8             // tokens per double-buffered batch

// Scratch (every element written exactly once per launch -> deterministic)
__device__ float g_part[LP * B * S * D];   // 32 MB partial segment sums
__device__ float g_cntp[B * LP * S];       // per-(b,lp,s) chunk counts
__device__ float g_cos[B * S];

// ---------------------------------------------------------------------------
// Kernel 1: partial segment sums. blockIdx = (d-part, batch, token-chunk).
// Thread owns one d-column of acc[S][DW] -> conflict-free scatter-add.
// SCALAR double buffer (R13-proven): batch k+1 loads into w[] while v[] is
// consumed; the loop-carried w->v dependency forces 8 loads in flight during
// every consume phase at ~40 regs.
// ---------------------------------------------------------------------------
__global__ __launch_bounds__(TPB) void k_accum(const int* __restrict__ attr,
                                               const float* __restrict__ text) {
    __shared__ float       acc[S * DW];    // 16 KB
    __shared__ signed char slab[LCH];      // 256 B (label-1; -1 = skip)
    __shared__ int         scnt[S];

    const int dp  = blockIdx.x;
    const int b   = blockIdx.y;
    const int lp  = blockIdx.z;
    const int tid = threadIdx.x;

    #pragma unroll
    for (int i = tid; i < S * DW; i += TPB) acc[i] = 0.0f;
    if (tid < S) scnt[tid] = 0;

    const int* ab = attr + b * L + lp * LCH;
    for (int i = tid; i < LCH; i += TPB) slab[i] = (signed char)(ab[i] - 1);
    __syncthreads();

    const float* tb = text + (size_t)b * L * D + (size_t)lp * LCH * D
                           + dp * DW + tid;

    float v[U];
    int   lv[U / 4];
    #pragma unroll
    for (int u = 0; u < U; u++) v[u] = __ldcs(tb + (size_t)u * D);
    #pragma unroll
    for (int j = 0; j < U / 4; j++) lv[j] = ((const int*)slab)[j];

    const int NB = LCH / U;
    #pragma unroll 1
    for (int k = 0; k < NB; k++) {
        float w[U];
        int   lw[U / 4];
        if (k + 1 < NB) {                       // prefetch batch k+1
            const float* nb = tb + (size_t)(k + 1) * U * D;
            #pragma unroll
            for (int u = 0; u < U; u++) w[u] = __ldcs(nb + (size_t)u * D);
            #pragma unroll
            for (int j = 0; j < U / 4; j++)
                lw[j] = ((const int*)slab)[(k + 1) * (U / 4) + j];
        }
        #pragma unroll
        for (int u = 0; u < U; u++) {           // consume batch k
            int s = (lv[u >> 2] << (24 - 8 * (u & 3))) >> 24;  // sign-extend
            if (s >= 0) acc[s * DW + tid] += v[u];   // uniform s per warp
        }
        if (k + 1 < NB) {
            #pragma unroll
            for (int u = 0; u < U; u++) v[u] = w[u];
            #pragma unroll
            for (int j = 0; j < U / 4; j++) lv[j] = lw[j];
        }
    }

    // per-chunk counts (dp==0 CTA only; shared atomics, deterministic)
    if (dp == 0) {
        for (int i = tid; i < LCH; i += TPB) {
            int s = slab[i];
            if (s >= 0) atomicAdd(&scnt[s], 1);
        }
    }
    __syncthreads();

    float* outp = g_part + ((size_t)lp * B + b) * S * D + dp * DW + tid;
    #pragma unroll
    for (int s = 0; s < S; s++) outp[(size_t)s * D] = acc[s * DW + tid];
    if (dp == 0 && tid < S) g_cntp[(b * LP + lp) * S + tid] = (float)scnt[tid];
}

// ---------------------------------------------------------------------------
// Kernel 2: per-(b,s) cosine; folds the LP=4 partials inline.
// ---------------------------------------------------------------------------
__global__ __launch_bounds__(128) void k_cos(const float* __restrict__ Vgs) {
    const int bs  = blockIdx.x;     // b*S + s
    const int b   = bs / S;
    const int tid = threadIdx.x;

    const float4* vg = (const float4*)(Vgs + (size_t)bs * D);
    const float4* p0 = (const float4*)(g_part + ((size_t)0 * B * S + bs) * D);
    const float4* p1 = (const float4*)(g_part + ((size_t)1 * B * S + bs) * D);
    const float4* p2 = (const float4*)(g_part + ((size_t)2 * B * S + bs) * D);
    const float4* p3 = (const float4*)(g_part + ((size_t)3 * B * S + bs) * D);

    const int sloc = bs - b * S;
    float cnt = 0.0f;
    #pragma unroll
    for (int lp = 0; lp < LP; lp++) cnt += g_cntp[(b * LP + lp) * S + sloc];
    const float inv = (cnt > 0.0f) ? (1.0f / cnt) : 0.0f;

    float dvm = 0.0f, dmm = 0.0f, dvv = 0.0f;
    #pragma unroll 2
    for (int d = tid; d < D / 4; d += 128) {
        float4 a0 = p0[d], a1 = p1[d], a2 = p2[d], a3 = p3[d];
        float4 v  = vg[d];
        float mx = ((a0.x + a1.x) + (a2.x + a3.x)) * inv;
        float my = ((a0.y + a1.y) + (a2.y + a3.y)) * inv;
        float mz = ((a0.z + a1.z) + (a2.z + a3.z)) * inv;
        float mw = ((a0.w + a1.w) + (a2.w + a3.w)) * inv;
        dvm = fmaf(v.x, mx, fmaf(v.y, my, fmaf(v.z, mz, fmaf(v.w, mw, dvm))));
        dmm = fmaf(mx, mx, fmaf(my, my, fmaf(mz, mz, fmaf(mw, mw, dmm))));
        dvv = fmaf(v.x, v.x, fmaf(v.y, v.y, fmaf(v.z, v.z, fmaf(v.w, v.w, dvv))));
    }
    #pragma unroll
    for (int o = 16; o > 0; o >>= 1) {
        dvm += __shfl_down_sync(0xFFFFFFFFu, dvm, o);
        dmm += __shfl_down_sync(0xFFFFFFFFu, dmm, o);
        dvv += __shfl_down_sync(0xFFFFFFFFu, dvv, o);
    }
    __shared__ float r0[4], r1[4], r2[4];
    const int w = tid >> 5, lane = tid & 31;
    if (lane == 0) { r0[w] = dvm; r1[w] = dmm; r2[w] = dvv; }
    __syncthreads();
    if (tid == 0) {
        float a  = r0[0] + r0[1] + r0[2] + r0[3];
        float m2 = r1[0] + r1[1] + r1[2] + r1[3];
        float v2 = r2[0] + r2[1] + r2[2] + r2[3];
        float denom = fmaxf(sqrtf(v2) * sqrtf(m2), 1e-8f);
        g_cos[bs] = a / denom;
    }
}

// ---------------------------------------------------------------------------
// Kernel 3: deterministic reduction of 2048 cosines -> scalar loss.
// ---------------------------------------------------------------------------
__global__ __launch_bounds__(1024) void k_final(float* __restrict__ out) {
    const int tid = threadIdx.x;
    float v = g_cos[tid] + g_cos[tid + 1024];
    #pragma unroll
    for (int o = 16; o > 0; o >>= 1) v += __shfl_down_sync(0xFFFFFFFFu, v, o);
    __shared__ float sh[32];
    if ((tid & 31) == 0) sh[tid >> 5] = v;
    __syncthreads();
    if (tid < 32) {
        float x = sh[tid];
        #pragma unroll
        for (int o = 16; o > 0; o >>= 1) x += __shfl_down_sync(0xFFFFFFFFu, x, o);
        if (tid == 0) out[0] = 1.0f - x / (float)(B * S);
    }
}

// ---------------------------------------------------------------------------
extern "C" void kernel_launch(void* const* d_in, const int* in_sizes, int n_in,
                              void* d_out, int out_size) {
    const int*   attr = (const int*)d_in[0];
    const float* text = (const float*)d_in[1];
    const float* vgs  = (const float*)d_in[2];
    float*       out  = (float*)d_out;

    dim3 g1(DP, B, LP);
    k_accum<<<g1, TPB>>>(attr, text);
    k_cos<<<B * S, 128>>>(vgs);
    k_final<<<1, 1024>>>(out);
}

// round 16
// speedup vs baseline: 1.3103x; 1.3103x over previous
#include <cuda_runtime.h>
#include <cuda_bf16.h>

#define B 64
#define L 1024
#define D 1024
#define S 32

#define DP 8            // d-partitions; each CTA covers 128 floats
#define DW 128
#define LP 2            // token-chunk partitions (R13-proven geometry)
#define LCH (L / LP)    // 512 tokens per CTA
#define TPB 128
#define U 16            // tokens per double-buffered batch (2 KB/warp in flight)

// Scratch (every element written exactly once per launch -> deterministic)
__device__ float g_part[LP * B * S * D];   // 16 MB partial segment sums
__device__ float g_cntp[B * LP * S];       // per-(b,lp,s) chunk counts
__device__ float g_cos[B * S];

// ---------------------------------------------------------------------------
// Kernel 1: partial segment sums. blockIdx = (d-part, batch, token-chunk).
// Thread owns one d-column of acc[S][DW] -> conflict-free scatter-add.
// SCALAR double buffer, U=16: batch k+1 loads into w[] while v[] is consumed;
// the loop-carried w->v dependency structurally forces 16 loads in flight
// during every consume phase.
// ---------------------------------------------------------------------------
__global__ __launch_bounds__(TPB) void k_accum(const int* __restrict__ attr,
                                               const float* __restrict__ text) {
    __shared__ float       acc[S * DW];    // 16 KB
    __shared__ signed char slab[LCH];      // 512 B (label-1; -1 = skip)
    __shared__ int         scnt[S];

    const int dp  = blockIdx.x;
    const int b   = blockIdx.y;
    const int lp  = blockIdx.z;
    const int tid = threadIdx.x;

    #pragma unroll
    for (int i = tid; i < S * DW; i += TPB) acc[i] = 0.0f;
    if (tid < S) scnt[tid] = 0;

    const int* ab = attr + b * L + lp * LCH;
    for (int i = tid; i < LCH; i += TPB) slab[i] = (signed char)(ab[i] - 1);
    __syncthreads();

    const float* tb = text + (size_t)b * L * D + (size_t)lp * LCH * D
                           + dp * DW + tid;

    float v[U];
    int   lv[U / 4];
    #pragma unroll
    for (int u = 0; u < U; u++) v[u] = __ldcs(tb + (size_t)u * D);
    #pragma unroll
    for (int j = 0; j < U / 4; j++) lv[j] = ((const int*)slab)[j];

    const int NB = LCH / U;
    #pragma unroll 1
    for (int k = 0; k < NB; k++) {
        float w[U];
        int   lw[U / 4];
        if (k + 1 < NB) {                       // prefetch batch k+1
            const float* nb = tb + (size_t)(k + 1) * U * D;
            #pragma unroll
            for (int u = 0; u < U; u++) w[u] = __ldcs(nb + (size_t)u * D);
            #pragma unroll
            for (int j = 0; j < U / 4; j++)
                lw[j] = ((const int*)slab)[(k + 1) * (U / 4) + j];
        }
        #pragma unroll
        for (int u = 0; u < U; u++) {           // consume batch k
            int s = (lv[u >> 2] << (24 - 8 * (u & 3))) >> 24;  // sign-extend
            if (s >= 0) acc[s * DW + tid] += v[u];   // uniform s per warp
        }
        if (k + 1 < NB) {
            #pragma unroll
            for (int u = 0; u < U; u++) v[u] = w[u];
            #pragma unroll
            for (int j = 0; j < U / 4; j++) lv[j] = lw[j];
        }
    }

    // per-chunk counts (dp==0 CTA only; shared atomics, deterministic)
    if (dp == 0) {
        for (int i = tid; i < LCH; i += TPB) {
            int s = slab[i];
            if (s >= 0) atomicAdd(&scnt[s], 1);
        }
    }
    __syncthreads();

    float* outp = g_part + ((size_t)lp * B + b) * S * D + dp * DW + tid;
    #pragma unroll
    for (int s = 0; s < S; s++) outp[(size_t)s * D] = acc[s * DW + tid];
    if (dp == 0 && tid < S) g_cntp[(b * LP + lp) * S + tid] = (float)scnt[tid];
}

// ---------------------------------------------------------------------------
// Kernel 2 (R13 shape): per-(b,s) cosine; folds the LP=2 partials inline.
// ---------------------------------------------------------------------------
__global__ __launch_bounds__(128) void k_cos(const float* __restrict__ Vgs) {
    const int bs  = blockIdx.x;     // b*S + s
    const int b   = bs / S;
    const int tid = threadIdx.x;

    const float4* vg = (const float4*)(Vgs + (size_t)bs * D);
    const float4* p0 = (const float4*)(g_part + ((size_t)0 * B * S + bs) * D);
    const float4* p1 = (const float4*)(g_part + ((size_t)1 * B * S + bs) * D);

    const int sloc = bs - b * S;
    float cnt = 0.0f;
    #pragma unroll
    for (int lp = 0; lp < LP; lp++) cnt += g_cntp[(b * LP + lp) * S + sloc];
    const float inv = (cnt > 0.0f) ? (1.0f / cnt) : 0.0f;

    float dvm = 0.0f, dmm = 0.0f, dvv = 0.0f;
    #pragma unroll 2
    for (int d = tid; d < D / 4; d += 128) {
        float4 a0 = p0[d], a1 = p1[d];
        float4 v  = vg[d];
        float mx = (a0.x + a1.x) * inv;
        float my = (a0.y + a1.y) * inv;
        float mz = (a0.z + a1.z) * inv;
        float mw = (a0.w + a1.w) * inv;
        dvm = fmaf(v.x, mx, fmaf(v.y, my, fmaf(v.z, mz, fmaf(v.w, mw, dvm))));
        dmm = fmaf(mx, mx, fmaf(my, my, fmaf(mz, mz, fmaf(mw, mw, dmm))));
        dvv = fmaf(v.x, v.x, fmaf(v.y, v.y, fmaf(v.z, v.z, fmaf(v.w, v.w, dvv))));
    }
    #pragma unroll
    for (int o = 16; o > 0; o >>= 1) {
        dvm += __shfl_down_sync(0xFFFFFFFFu, dvm, o);
        dmm += __shfl_down_sync(0xFFFFFFFFu, dmm, o);
        dvv += __shfl_down_sync(0xFFFFFFFFu, dvv, o);
    }
    __shared__ float r0[4], r1[4], r2[4];
    const int w = tid >> 5, lane = tid & 31;
    if (lane == 0) { r0[w] = dvm; r1[w] = dmm; r2[w] = dvv; }
    __syncthreads();
    if (tid == 0) {
        float a  = r0[0] + r0[1] + r0[2] + r0[3];
        float m2 = r1[0] + r1[1] + r1[2] + r1[3];
        float v2 = r2[0] + r2[1] + r2[2] + r2[3];
        float denom = fmaxf(sqrtf(v2) * sqrtf(m2), 1e-8f);
        g_cos[bs] = a / denom;
    }
}

// ---------------------------------------------------------------------------
// Kernel 3: deterministic reduction of 2048 cosines -> scalar loss.
// ---------------------------------------------------------------------------
__global__ __launch_bounds__(1024) void k_final(float* __restrict__ out) {
    const int tid = threadIdx.x;
    float v = g_cos[tid] + g_cos[tid + 1024];
    #pragma unroll
    for (int o = 16; o > 0; o >>= 1) v += __shfl_down_sync(0xFFFFFFFFu, v, o);
    __shared__ float sh[32];
    if ((tid & 31) == 0) sh[tid >> 5] = v;
    __syncthreads();
    if (tid < 32) {
        float x = sh[tid];
        #pragma unroll
        for (int o = 16; o > 0; o >>= 1) x += __shfl_down_sync(0xFFFFFFFFu, x, o);
        if (tid == 0) out[0] = 1.0f - x / (float)(B * S);
    }
}

// ---------------------------------------------------------------------------
extern "C" void kernel_launch(void* const* d_in, const int* in_sizes, int n_in,
                              void* d_out, int out_size) {
    const int*   attr = (const int*)d_in[0];
    const float* text = (const float*)d_in[1];
    const float* vgs  = (const float*)d_in[2];
    float*       out  = (float*)d_out;

    dim3 g1(DP, B, LP);
    k_accum<<<g1, TPB>>>(attr, text);
    k_cos<<<B * S, 128>>>(vgs);
    k_final<<<1, 1024>>>(out);
}